// round 5
// baseline (speedup 1.0000x reference)
#include <cuda_runtime.h>
#include <cstdint>

// Problem constants (fixed shapes from setup_inputs)
#define BB   16
#define NN   1536
#define CC   768
#define N0   3072
#define HH   64
#define WW   48
#define HW   (HH*WW)            // 3072
#define FM   (BB*HW*CC)         // 37,748,736 floats (151 MB)
#define NPTS (BB*N0)            // 49,152
#define EPSF 1e-6f

// Conv tiling
#define CH   16                 // channels per conv block (4 float4)
#define TY   8                  // output rows per conv block

// ---------------- device scratch (allocation-free) ----------------
__device__ __align__(16) float g_raw [FM];       // normalized token2map map
__device__ __align__(16) float g_cv  [FM];       // post-conv map
__device__ __align__(16) float g_wsum[BB*NN];    // sum(agg_w) -> 1/(sum+eps)
__device__ __align__(16) float g_wT  [9*CC];     // conv weights transposed [k][C]

__device__ int   g_ppix   [NPTS];                // pixel id per point
__device__ int   g_pix_cnt[BB*HW];
__device__ int   g_pix_off[BB*HW + 1];
__device__ int   g_pix_cur[BB*HW];
__device__ int   g_psrc   [NPTS];                // x-row index, pixel-list order
__device__ int   g_tok_cnt[BB*NN];
__device__ int   g_tok_off[BB*NN + 1];
__device__ int   g_tok_cur[BB*NN];
__device__ __align__(16) int4   g_tcorn[NPTS];   // 4 corner pixel ids, token-list order
__device__ __align__(16) float4 g_twt  [NPTS];   // 4 final weights,    token-list order

// pixel coords matching jnp: pos = 0.5*(clip(loc,-1,1)+1)*wh - 0.5, unfused to match rounding
__device__ __forceinline__ float pix_coord(float l, float wh) {
    l = fminf(fmaxf(l, -1.0f), 1.0f);
    float t = __fmul_rn(0.5f, __fadd_rn(l, 1.0f));
    return __fadd_rn(__fmul_rn(t, wh), -0.5f);
}

// ---------------- zero the small metadata arrays ----------------
__global__ void k_zero_meta() {
    int i = blockIdx.x * blockDim.x + threadIdx.x;
    if (i < BB*HW) g_pix_cnt[i] = 0;
    if (i < BB*NN) { g_tok_cnt[i] = 0; g_wsum[i] = 0.0f; }
}

// ---------------- per-point counts ----------------
__global__ void k_count(const float* __restrict__ loc_orig,
                        const int*   __restrict__ idx_agg,
                        const float* __restrict__ agg_w) {
    int p = blockIdx.x * blockDim.x + threadIdx.x;
    if (p >= NPTS) return;
    int b = p / N0;
    float px = pix_coord(loc_orig[2*p],   (float)WW);
    float py = pix_coord(loc_orig[2*p+1], (float)HH);
    int ix = min(max((int)rintf(px), 0), WW-1);   // rintf = round-half-even = jnp.round
    int iy = min(max((int)rintf(py), 0), HH-1);
    int pix = b*HW + iy*WW + ix;
    g_ppix[p] = pix;
    atomicAdd(&g_pix_cnt[pix], 1);
    int seg = b*NN + idx_agg[p];
    atomicAdd(&g_tok_cnt[seg], 1);
    atomicAdd(&g_wsum[seg], agg_w[p]);
}

// ---------------- exclusive scans (block 0: pixels, block 1: tokens) ----------------
__global__ __launch_bounds__(1024) void k_scan() {
    __shared__ int sm[1024];
    int t = threadIdx.x;
    int n; int *cnt, *off, *cur;
    if (blockIdx.x == 0) { n = BB*HW; cnt = g_pix_cnt; off = g_pix_off; cur = g_pix_cur; }
    else                 { n = BB*NN; cnt = g_tok_cnt; off = g_tok_off; cur = g_tok_cur; }
    int chunk = (n + 1023) >> 10;
    int s = t * chunk, e = min(s + chunk, n);
    int tot = 0;
    for (int i = s; i < e; i++) tot += cnt[i];
    sm[t] = tot; __syncthreads();
    #pragma unroll
    for (int d = 1; d < 1024; d <<= 1) {
        int v = (t >= d) ? sm[t - d] : 0;
        __syncthreads();
        sm[t] += v;
        __syncthreads();
    }
    int base = sm[t] - tot;                 // exclusive prefix for this thread's range
    for (int i = s; i < e; i++) { off[i] = base; cur[i] = base; base += cnt[i]; }
    if (t == 1023) off[n] = sm[1023];
}

// ---------------- weight transpose + wsum reciprocal ----------------
__global__ void k_prep(const float* __restrict__ conv_w) {
    int i = blockIdx.x * blockDim.x + threadIdx.x;
    if (i < 9*CC) {
        int c = i / 9, k = i % 9;           // conv_w layout [C][1][3][3]
        g_wT[k*CC + c] = conv_w[i];
    } else if (i < 9*CC + BB*NN) {
        int j = i - 9*CC;
        g_wsum[j] = 1.0f / (g_wsum[j] + EPSF);
    }
}

// ---------------- fill CSR lists + precompute per-point gather data ----------------
__global__ void k_fill(const float* __restrict__ loc_orig,
                       const int*   __restrict__ idx_agg,
                       const float* __restrict__ agg_w) {
    int p = blockIdx.x * blockDim.x + threadIdx.x;
    if (p >= NPTS) return;
    int b = p / N0;
    int tok = idx_agg[p];
    int seg = b*NN + tok;

    // pixel-ordered source row list
    int pos = atomicAdd(&g_pix_cur[g_ppix[p]], 1);
    g_psrc[pos] = b*NN + tok;

    // token-ordered bilinear corners + final weights
    int tp = atomicAdd(&g_tok_cur[seg], 1);
    float px = pix_coord(loc_orig[2*p],   (float)WW);
    float py = pix_coord(loc_orig[2*p+1], (float)HH);
    int x0 = min(max((int)floorf(px), 0), WW-1);
    int y0 = min(max((int)floorf(py), 0), HH-1);
    int x1 = min(x0 + 1, WW-1);
    int y1 = min(y0 + 1, HH-1);
    float wx = fminf((float)x1, px) - (float)x0;   // reference border quirk
    float wy = fminf((float)y1, py) - (float)y0;
    float sc = agg_w[p] * g_wsum[seg];             // agg_w / (wsum+eps)
    int base = b*HW;
    g_tcorn[tp] = make_int4(base + y0*WW + x0, base + y0*WW + x1,
                            base + y1*WW + x0, base + y1*WW + x1);
    g_twt[tp] = make_float4((1.0f-wx)*(1.0f-wy)*sc, wx*(1.0f-wy)*sc,
                            (1.0f-wx)*wy*sc,        wx*wy*sc);
}

// ---------------- scatter-as-gather: one block per pixel, no atomics, MLP=4 ----------------
__global__ __launch_bounds__(192) void k_scatter_csr(const float* __restrict__ x) {
    int gp = blockIdx.x;                    // global pixel
    int s = g_pix_off[gp], e = g_pix_off[gp+1];
    int c4 = threadIdx.x;                   // 192 = CC/4
    float4 acc = make_float4(0.f, 0.f, 0.f, 0.f);
    for (int i0 = s; i0 < e; i0 += 4) {
        int m = e - i0;
        int src[4];
        float4 v[4];
        #pragma unroll
        for (int j = 0; j < 4; j++)
            if (j < m) src[j] = __ldg(&g_psrc[i0+j]);
        #pragma unroll
        for (int j = 0; j < 4; j++)
            if (j < m) v[j] = __ldg((const float4*)(x + (size_t)src[j]*CC) + c4);
        #pragma unroll
        for (int j = 0; j < 4; j++)
            if (j < m) { acc.x += v[j].x; acc.y += v[j].y; acc.z += v[j].z; acc.w += v[j].w; }
    }
    float rc = 1.0f / ((float)(e - s) + EPSF);
    acc.x *= rc; acc.y *= rc; acc.z *= rc; acc.w *= rc;
    ((float4*)(g_raw + (size_t)gp*CC))[c4] = acc;
}

// ---------------- tiled depthwise 3x3 conv ----------------
__global__ __launch_bounds__(192) void k_conv(const float* __restrict__ conv_b) {
    __shared__ float4 sm[(TY+2)*WW*(CH/4)];   // 30 KB
    const int ty0   = blockIdx.x * TY;
    const int cbase = blockIdx.y * CH;
    const int b     = blockIdx.z;
    const int tid   = threadIdx.x;

    for (int idx = tid; idx < (TY+2)*WW*(CH/4); idx += 192) {
        int c4  = idx & 3;
        int pix = idx >> 2;
        int xx  = pix % WW;
        int row = pix / WW;
        int gy  = ty0 + row - 1;
        float4 v = make_float4(0.f, 0.f, 0.f, 0.f);
        if (gy >= 0 && gy < HH)
            v = *(const float4*)(g_raw + (size_t)(b*HW + gy*WW + xx)*CC + cbase + 4*c4);
        sm[idx] = v;
    }
    __syncthreads();

    const int c4 = tid & 3;
    const int xx = tid >> 2;

    float4 w[9];
    #pragma unroll
    for (int k = 0; k < 9; k++)
        w[k] = *(const float4*)(g_wT + k*CC + cbase + 4*c4);
    const float4 bias = *(const float4*)(conv_b + cbase + 4*c4);

    float4 L[3], M[3], R[3];
    const bool hasL = (xx > 0), hasR = (xx < WW-1);
    float4 z = make_float4(0.f, 0.f, 0.f, 0.f);
    #pragma unroll
    for (int r = 0; r < 3; r++) {
        L[r] = hasL ? sm[(r*WW + xx-1)*4 + c4] : z;
        M[r] =        sm[(r*WW + xx  )*4 + c4];
        R[r] = hasR ? sm[(r*WW + xx+1)*4 + c4] : z;
    }

    #pragma unroll
    for (int oy = 0; oy < TY; oy++) {
        float4 acc = bias;
        #pragma unroll
        for (int r = 0; r < 3; r++) {
            acc.x += L[r].x*w[r*3+0].x + M[r].x*w[r*3+1].x + R[r].x*w[r*3+2].x;
            acc.y += L[r].y*w[r*3+0].y + M[r].y*w[r*3+1].y + R[r].y*w[r*3+2].y;
            acc.z += L[r].z*w[r*3+0].z + M[r].z*w[r*3+1].z + R[r].z*w[r*3+2].z;
            acc.w += L[r].w*w[r*3+0].w + M[r].w*w[r*3+1].w + R[r].w*w[r*3+2].w;
        }
        *(float4*)(g_cv + (size_t)(b*HW + (ty0+oy)*WW + xx)*CC + cbase + 4*c4) = acc;
        if (oy < TY-1) {
            int r = oy + 3;
            L[0]=L[1]; L[1]=L[2]; L[2] = hasL ? sm[(r*WW + xx-1)*4 + c4] : z;
            M[0]=M[1]; M[1]=M[2]; M[2] =        sm[(r*WW + xx  )*4 + c4];
            R[0]=R[1]; R[1]=R[2]; R[2] = hasR ? sm[(r*WW + xx+1)*4 + c4] : z;
        }
    }
}

// ---------------- token gather: one block per token, precomputed corners, MLP=8 ----------------
__global__ __launch_bounds__(192) void k_gather_csr(float* __restrict__ out) {
    int gt = blockIdx.x;                    // global token segment (b*NN + n)
    int s = g_tok_off[gt], e = g_tok_off[gt+1];
    int c4 = threadIdx.x;
    float4 acc = make_float4(0.f, 0.f, 0.f, 0.f);
    for (int i0 = s; i0 < e; i0 += 2) {
        int m = e - i0;
        int4   cn[2];
        float4 wt[2];
        float4 v[2][4];
        #pragma unroll
        for (int j = 0; j < 2; j++)
            if (j < m) { cn[j] = __ldg(&g_tcorn[i0+j]); wt[j] = __ldg(&g_twt[i0+j]); }
        #pragma unroll
        for (int j = 0; j < 2; j++) {
            if (j < m) {
                v[j][0] = __ldg((const float4*)(g_cv + (size_t)cn[j].x*CC) + c4);
                v[j][1] = __ldg((const float4*)(g_cv + (size_t)cn[j].y*CC) + c4);
                v[j][2] = __ldg((const float4*)(g_cv + (size_t)cn[j].z*CC) + c4);
                v[j][3] = __ldg((const float4*)(g_cv + (size_t)cn[j].w*CC) + c4);
            }
        }
        #pragma unroll
        for (int j = 0; j < 2; j++) {
            if (j < m) {
                acc.x += wt[j].x*v[j][0].x + wt[j].y*v[j][1].x + wt[j].z*v[j][2].x + wt[j].w*v[j][3].x;
                acc.y += wt[j].x*v[j][0].y + wt[j].y*v[j][1].y + wt[j].z*v[j][2].y + wt[j].w*v[j][3].y;
                acc.z += wt[j].x*v[j][0].z + wt[j].y*v[j][1].z + wt[j].z*v[j][2].z + wt[j].w*v[j][3].z;
                acc.w += wt[j].x*v[j][0].w + wt[j].y*v[j][1].w + wt[j].z*v[j][2].w + wt[j].w*v[j][3].w;
            }
        }
    }
    ((float4*)(out + (size_t)gt*CC))[c4] = acc;
}

// ---------------- launch ----------------
extern "C" void kernel_launch(void* const* d_in, const int* in_sizes, int n_in,
                              void* d_out, int out_size) {
    const float* x        = (const float*)d_in[0];
    const float* loc_orig = (const float*)d_in[2];
    const int*   idx_agg  = (const int*)  d_in[3];
    const float* agg_w    = (const float*)d_in[4];
    const float* conv_w   = (const float*)d_in[n_in-2];
    const float* conv_b   = (const float*)d_in[n_in-1];
    float* out = (float*)d_out;

    // setup: zero meta, counts, scans, reciprocals, CSR fill with precomputed gather data
    k_zero_meta<<<(BB*HW + 255)/256, 256>>>();
    k_count<<<(NPTS + 255)/256, 256>>>(loc_orig, idx_agg, agg_w);
    k_scan<<<2, 1024>>>();
    k_prep<<<(9*CC + BB*NN + 255)/256, 256>>>(conv_w);
    k_fill<<<(NPTS + 255)/256, 256>>>(loc_orig, idx_agg, agg_w);

    // three full-size stages (no atomics, short dependency chains)
    k_scatter_csr<<<BB*HW, 192>>>(x);
    {
        dim3 cgrid(HH/TY, CC/CH, BB);   // 8 x 48 x 16
        k_conv<<<cgrid, 192>>>(conv_b);
    }
    k_gather_csr<<<BB*NN, 192>>>(out);
}

// round 6
// speedup vs baseline: 1.4760x; 1.4760x over previous
#include <cuda_runtime.h>
#include <cuda_fp16.h>
#include <cstdint>

// Problem constants (fixed shapes from setup_inputs)
#define BB   16
#define NN   1536
#define CC   768
#define N0   3072
#define HH   64
#define WW   48
#define HW   (HH*WW)            // 3072
#define FM   (BB*HW*CC)         // 37,748,736 elements
#define NPTS (BB*N0)            // 49,152
#define EPSF 1e-6f

// Scratch (device globals: allocation-free, per harness rules)
__device__ __align__(16) float  g_raw [FM];      // token2map accumulation, [B][HW][C] fp32
__device__ __align__(16) __half g_cv  [FM];      // post-conv map,          [B][HW][C] fp16
__device__ __align__(16) float  g_cnt [BB*HW];   // hit count -> 1/(cnt+eps)
__device__ __align__(16) float  g_wsum[BB*NN];   // sum(agg_w) -> 1/(sum+eps)
__device__ __align__(16) float  g_wT  [9*CC];    // conv weights transposed [k][C]

__device__ __forceinline__ void red_add4(float* p, float4 v) {
    asm volatile("red.global.add.v4.f32 [%0], {%1,%2,%3,%4};"
                 :: "l"(p), "f"(v.x), "f"(v.y), "f"(v.z), "f"(v.w) : "memory");
}

// pixel coords matching jnp: pos = 0.5*(clip(loc,-1,1)+1)*wh - 0.5, unfused to match rounding
__device__ __forceinline__ float pix_coord(float l, float wh) {
    l = fminf(fmaxf(l, -1.0f), 1.0f);
    float t = __fmul_rn(0.5f, __fadd_rn(l, 1.0f));
    return __fadd_rn(__fmul_rn(t, wh), -0.5f);
}

// ---------------- zeroing ----------------
__global__ void k_zero_scratch() {
    const int n_raw4 = FM/4, n_cnt4 = (BB*HW)/4, n_ws4 = (BB*NN)/4;
    int i = blockIdx.x * blockDim.x + threadIdx.x;
    float4 z = make_float4(0.f, 0.f, 0.f, 0.f);
    if (i < n_raw4)                       ((float4*)g_raw )[i] = z;
    else if (i < n_raw4 + n_cnt4)         ((float4*)g_cnt )[i - n_raw4] = z;
    else if (i < n_raw4 + n_cnt4 + n_ws4) ((float4*)g_wsum)[i - n_raw4 - n_cnt4] = z;
}

__global__ void k_zero_out(float4* out, int n4) {
    int i = blockIdx.x * blockDim.x + threadIdx.x;
    if (i < n4) out[i] = make_float4(0.f, 0.f, 0.f, 0.f);
}

// ---------------- counts + weight sums ----------------
__global__ void k_count(const float* __restrict__ loc_orig,
                        const int*   __restrict__ idx_agg,
                        const float* __restrict__ agg_w) {
    int p = blockIdx.x * blockDim.x + threadIdx.x;
    if (p >= NPTS) return;
    int b = p / N0;
    float px = pix_coord(loc_orig[2*p],   (float)WW);
    float py = pix_coord(loc_orig[2*p+1], (float)HH);
    int ix = min(max((int)rintf(px), 0), WW-1);   // rintf = round-half-even = jnp.round
    int iy = min(max((int)rintf(py), 0), HH-1);
    atomicAdd(&g_cnt[b*HW + iy*WW + ix], 1.0f);
    int tok = idx_agg[p];
    atomicAdd(&g_wsum[b*NN + tok], agg_w[p]);
}

// ---------------- reciprocals + weight transpose ----------------
__global__ void k_prep(const float* __restrict__ conv_w) {
    int i = blockIdx.x * blockDim.x + threadIdx.x;
    if (i < 9*CC) {
        int c = i / 9, k = i % 9;           // conv_w layout [C][1][3][3]
        g_wT[k*CC + c] = conv_w[i];
    } else if (i < 9*CC + BB*HW) {
        int j = i - 9*CC;
        g_cnt[j] = 1.0f / (g_cnt[j] + EPSF);
    } else if (i < 9*CC + BB*HW + BB*NN) {
        int j = i - 9*CC - BB*HW;
        g_wsum[j] = 1.0f / (g_wsum[j] + EPSF);
    }
}

// ---------------- feature scatter: x[b, idx_agg] -> raw map ----------------
__global__ __launch_bounds__(192) void k_scatter(const float* __restrict__ x,
                                                 const float* __restrict__ loc_orig,
                                                 const int*   __restrict__ idx_agg) {
    int p = blockIdx.x;
    int b = p / N0;
    float px = pix_coord(loc_orig[2*p],   (float)WW);
    float py = pix_coord(loc_orig[2*p+1], (float)HH);
    int ix = min(max((int)rintf(px), 0), WW-1);
    int iy = min(max((int)rintf(py), 0), HH-1);
    int pix = b*HW + iy*WW + ix;
    int tok = idx_agg[p];
    const float4* src = (const float4*)(x + ((size_t)b*NN + tok)*CC);
    float* dst = g_raw + (size_t)pix*CC;
    int c4 = threadIdx.x;                    // 192 threads, C/4 = 192
    float4 v = src[c4];
    red_add4(dst + 4*c4, v);
}

// ---------------- depthwise 3x3 conv, count-norm folded, fp16 output ----------------
__global__ __launch_bounds__(192) void k_conv(const float* __restrict__ conv_b) {
    int gp = blockIdx.x;                     // B*HW pixels
    int b  = gp / HW;
    int hw = gp - b*HW;
    int y  = hw / WW;
    int xx = hw - y*WW;
    int c4 = threadIdx.x;
    float4 acc = ((const float4*)conv_b)[c4];
    #pragma unroll
    for (int dy = -1; dy <= 1; dy++) {
        #pragma unroll
        for (int dx = -1; dx <= 1; dx++) {
            int ny = y + dy, nx = xx + dx;
            if (ny < 0 || ny >= HH || nx < 0 || nx >= WW) continue;
            int np = b*HW + ny*WW + nx;
            float rc = __ldg(&g_cnt[np]);
            int k = (dy+1)*3 + (dx+1);
            float4 v  = *(const float4*)(g_raw + (size_t)np*CC + 4*c4);
            float4 wv = *(const float4*)(g_wT  + k*CC          + 4*c4);
            acc.x += v.x * rc * wv.x;
            acc.y += v.y * rc * wv.y;
            acc.z += v.z * rc * wv.z;
            acc.w += v.w * rc * wv.w;
        }
    }
    // store 4 channels as 2 half2 (8 bytes)
    __half2 h0 = __float22half2_rn(make_float2(acc.x, acc.y));
    __half2 h1 = __float22half2_rn(make_float2(acc.z, acc.w));
    uint2 pk;
    pk.x = *(unsigned int*)&h0;
    pk.y = *(unsigned int*)&h1;
    ((uint2*)(g_cv + (size_t)gp*CC))[c4] = pk;
}

// ---------------- bilinear gather (fp16 map) + weighted scatter to tokens ----------------
__device__ __forceinline__ float4 ld_half4(const __half* row, int c4) {
    uint2 pk = __ldg((const uint2*)row + c4);
    __half2 h0 = *(__half2*)&pk.x;
    __half2 h1 = *(__half2*)&pk.y;
    float2 f0 = __half22float2(h0);
    float2 f1 = __half22float2(h1);
    return make_float4(f0.x, f0.y, f1.x, f1.y);
}

__global__ __launch_bounds__(192) void k_gather(const float* __restrict__ loc_orig,
                                                const int*   __restrict__ idx_agg,
                                                const float* __restrict__ agg_w,
                                                float*       __restrict__ out) {
    int p = blockIdx.x;
    int b = p / N0;
    float px = pix_coord(loc_orig[2*p],   (float)WW);
    float py = pix_coord(loc_orig[2*p+1], (float)HH);
    int x0 = min(max((int)floorf(px), 0), WW-1);
    int y0 = min(max((int)floorf(py), 0), HH-1);
    int x1 = min(x0 + 1, WW-1);
    int y1 = min(y0 + 1, HH-1);
    float wx = fminf((float)x1, px) - (float)x0;   // replicates reference border quirk
    float wy = fminf((float)y1, py) - (float)y0;
    float w00 = (1.0f-wx)*(1.0f-wy);
    float w10 = wx*(1.0f-wy);
    float w01 = (1.0f-wx)*wy;
    float w11 = wx*wy;
    int base = b*HW;
    const __half* r00 = g_cv + (size_t)(base + y0*WW + x0)*CC;
    const __half* r10 = g_cv + (size_t)(base + y0*WW + x1)*CC;
    const __half* r01 = g_cv + (size_t)(base + y1*WW + x0)*CC;
    const __half* r11 = g_cv + (size_t)(base + y1*WW + x1)*CC;
    int tok = idx_agg[p];
    float scale = agg_w[p] * g_wsum[b*NN + tok];   // w / (wsum + eps)
    float* dst = out + ((size_t)b*NN + tok)*CC;
    int c4 = threadIdx.x;
    float4 a  = ld_half4(r00, c4);
    float4 bq = ld_half4(r10, c4);
    float4 cq = ld_half4(r01, c4);
    float4 dq = ld_half4(r11, c4);
    float4 v;
    v.x = (w00*a.x + w10*bq.x + w01*cq.x + w11*dq.x) * scale;
    v.y = (w00*a.y + w10*bq.y + w01*cq.y + w11*dq.y) * scale;
    v.z = (w00*a.z + w10*bq.z + w01*cq.z + w11*dq.z) * scale;
    v.w = (w00*a.w + w10*bq.w + w01*cq.w + w11*dq.w) * scale;
    red_add4(dst + 4*c4, v);
}

// ---------------- launch ----------------
extern "C" void kernel_launch(void* const* d_in, const int* in_sizes, int n_in,
                              void* d_out, int out_size) {
    const float* x        = (const float*)d_in[0];
    const float* loc_orig = (const float*)d_in[2];
    const int*   idx_agg  = (const int*)  d_in[3];
    const float* agg_w    = (const float*)d_in[4];
    const float* conv_w   = (const float*)d_in[n_in-2];
    const float* conv_b   = (const float*)d_in[n_in-1];
    float* out = (float*)d_out;

    // zero scratch + output
    {
        int total4 = FM/4 + (BB*HW)/4 + (BB*NN)/4;
        k_zero_scratch<<<(total4 + 255)/256, 256>>>();
        int n4 = out_size / 4;
        k_zero_out<<<(n4 + 255)/256, 256>>>((float4*)out, n4);
    }
    // per-pixel counts + per-token weight sums
    k_count<<<(NPTS + 255)/256, 256>>>(loc_orig, idx_agg, agg_w);
    // reciprocals + weight transpose
    {
        int total = 9*CC + BB*HW + BB*NN;
        k_prep<<<(total + 255)/256, 256>>>(conv_w);
    }
    // feature scatter to map
    k_scatter<<<NPTS, 192>>>(x, loc_orig, idx_agg);
    // depthwise conv (normalization folded), fp16 output map
    k_conv<<<BB*HW, 192>>>(conv_b);
    // bilinear gather + token aggregation
    k_gather<<<NPTS, 192>>>(loc_orig, idx_agg, agg_w, out);
}